// round 4
// baseline (speedup 1.0000x reference)
#include <cuda_runtime.h>
#include <math.h>

#define NN     50000
#define NEDGE  600000
#define HDIM   128
#define NPASS  5
#define LN_EPS 1e-6f

#define NODE_TILES ((NN + 63) / 64)   // 782
#define EDGE_TILES (NEDGE / 64)       // 9375 (exact)

typedef unsigned long long ull;

// Persistent device scratch
__device__ float g_n[NN * HDIM];        // node features
__device__ float g_S[NN * HDIM];        // per-pass scatter of n[sender]
__device__ float g_hsum[NN * HDIM];     // sum of edge hidden h over receivers
__device__ float g_deg[NN];             // in-degree (float)
__device__ float g_cagg[NN * HDIM];     // loop-invariant agg contribution @ W0_bot
__device__ float g_T1[HDIM * HDIM];     // W1e @ Wm_bot
__device__ float g_tvec[HDIM];          // b1e @ Wm_bot
__device__ float g_Wg[HDIM * HDIM];     // W1e @ Wm_bot @ W0_bot
__device__ float g_bg[HDIM];            // b1e @ Wm_bot @ W0_bot
__device__ float g_Wf[HDIM * HDIM];     // Wm_top @ W0_bot

// ---------------------------------------------------------------------------
// f32x2 packed helpers
// ---------------------------------------------------------------------------
__device__ __forceinline__ ull pk2(float x, float y) {
    ull r; asm("mov.b64 %0, {%1, %2};" : "=l"(r) : "f"(x), "f"(y)); return r;
}
__device__ __forceinline__ float2 upk2(ull v) {
    float2 f; asm("mov.b64 {%0, %1}, %2;" : "=f"(f.x), "=f"(f.y) : "l"(v)); return f;
}
#define FMA2(acc, a, b) asm("fma.rn.f32x2 %0, %1, %2, %0;" : "+l"(acc) : "l"(a), "l"(b))

// ---------------------------------------------------------------------------
// Packed register-tiled GEMM micro-step. Block = 256 thr. Tile 64 x 128.
// A2: duplicated-pair A in smem, [64][LDA] ull. B_s: [KC][128] float.
// acc[r][0] covers cols (j, j+1), acc[r][1] covers (j+2, j+3).
// ---------------------------------------------------------------------------
template<int KC, int LDA>
__device__ __forceinline__ void gemm2_step(const ull* __restrict__ A2,
                                           const float* __restrict__ B_s,
                                           int m0, int j, ull acc[8][2]) {
#pragma unroll 8
    for (int kk = 0; kk < KC; kk++) {
        ulonglong2 b = *(const ulonglong2*)(B_s + kk * HDIM + j);
#pragma unroll
        for (int r = 0; r < 8; r++) {
            ull a = A2[(m0 + r) * LDA + kk];
            FMA2(acc[r][0], a, b.x);
            FMA2(acc[r][1], a, b.y);
        }
    }
}

// ---------------------------------------------------------------------------
// Weight folds
// ---------------------------------------------------------------------------
__global__ void k_fold1(const float* __restrict__ W1e, const float* __restrict__ b1e,
                        const float* __restrict__ Wm) {
    __shared__ float a[HDIM];
    int j = threadIdx.x;
    a[j] = (blockIdx.x < 128) ? W1e[blockIdx.x * HDIM + j] : b1e[j];
    __syncthreads();
    float s = 0.f;
#pragma unroll 8
    for (int l = 0; l < HDIM; l++)
        s = fmaf(a[l], Wm[(HDIM + l) * HDIM + j], s);
    if (blockIdx.x < 128) g_T1[blockIdx.x * HDIM + j] = s;
    else                  g_tvec[j] = s;
}

__global__ void k_fold2(const float* __restrict__ W0n, const float* __restrict__ Wm) {
    __shared__ float a[HDIM];
    int j = threadIdx.x;
    int bid = blockIdx.x;
    if (bid < 128)       a[j] = g_T1[bid * HDIM + j];
    else if (bid == 128) a[j] = g_tvec[j];
    else                 a[j] = Wm[(bid - 129) * HDIM + j];   // Wm_top rows
    __syncthreads();
    float s = 0.f;
#pragma unroll 8
    for (int l = 0; l < HDIM; l++)
        s = fmaf(a[l], W0n[(HDIM + l) * HDIM + j], s);        // W0_bot
    if (bid < 128)       g_Wg[bid * HDIM + j] = s;
    else if (bid == 128) g_bg[j] = s;
    else                 g_Wf[(bid - 129) * HDIM + j] = s;
}

// ---------------------------------------------------------------------------
// Zero helpers
// ---------------------------------------------------------------------------
__global__ void k_zero_pre() {   // zero g_hsum and g_deg
    int i = blockIdx.x * blockDim.x + threadIdx.x;
    if (i < NN * 32) ((float4*)g_hsum)[i] = make_float4(0.f, 0.f, 0.f, 0.f);
    else {
        int d = i - NN * 32;
        if (d < NN / 4) ((float4*)g_deg)[d] = make_float4(0.f, 0.f, 0.f, 0.f);
    }
}
__global__ void k_zero_S() {
    int i = blockIdx.x * blockDim.x + threadIdx.x;
    if (i < NN * 32) ((float4*)g_S)[i] = make_float4(0.f, 0.f, 0.f, 0.f);
}

// Shared-memory layout for the big GEMM kernels (bytes):
//   A2  : [64][33] ull   -> 16896
//   h_s : [64][132] float-> 33792
//   B_s : [32][128] float-> 16384
#define OFF_A2  0
#define OFF_H   (64 * 33 * 8)
#define OFF_B   (OFF_H + 64 * 132 * 4)
#define SM_BIG  (OFF_B + 32 * 128 * 4)          // 67072

// ---------------------------------------------------------------------------
// Node encoder: n = relu(x@W0+b0)@W1+b1
// ---------------------------------------------------------------------------
__global__ void k_node_enc(const float* __restrict__ x,
                           const float* __restrict__ W0, const float* __restrict__ b0,
                           const float* __restrict__ W1, const float* __restrict__ b1) {
    extern __shared__ char smraw[];
    ull*   A2  = (ull*)(smraw + OFF_A2);
    float* h_s = (float*)(smraw + OFF_H);
    float* B_s = (float*)(smraw + OFF_B);

    const int tid = threadIdx.x;
    const int ty = tid >> 5, tx = tid & 31;
    const int m0 = ty * 8;
    const int j  = tx * 4;
    const int row0 = blockIdx.x * 64;

    // layer 1: K = 32
#pragma unroll
    for (int i = 0; i < 8; i++) {
        int idx = tid + i * 256;
        int m = idx >> 5, kk = idx & 31;
        int gr = row0 + m;
        float v = (gr < NN) ? x[gr * 32 + kk] : 0.f;
        A2[m * 33 + kk] = pk2(v, v);
    }
#pragma unroll
    for (int i = 0; i < 16; i++) B_s[tid + i * 256] = W0[tid + i * 256];
    __syncthreads();

    ull acc[8][2];
    {
        float4 bv = *(const float4*)(b0 + j);
#pragma unroll
        for (int r = 0; r < 8; r++) { acc[r][0] = pk2(bv.x, bv.y); acc[r][1] = pk2(bv.z, bv.w); }
    }
    gemm2_step<32, 33>(A2, B_s, m0, j, acc);
    __syncthreads();

#pragma unroll
    for (int r = 0; r < 8; r++) {
        float2 p0 = upk2(acc[r][0]), p1 = upk2(acc[r][1]);
        float4 h;
        h.x = fmaxf(p0.x, 0.f); h.y = fmaxf(p0.y, 0.f);
        h.z = fmaxf(p1.x, 0.f); h.w = fmaxf(p1.y, 0.f);
        *(float4*)(h_s + (m0 + r) * 132 + j) = h;
    }

    // layer 2: K = 128 in 4 chunks
    ull o[8][2];
    {
        float4 bv = *(const float4*)(b1 + j);
#pragma unroll
        for (int r = 0; r < 8; r++) { o[r][0] = pk2(bv.x, bv.y); o[r][1] = pk2(bv.z, bv.w); }
    }
    for (int c = 0; c < 4; c++) {
        __syncthreads();
#pragma unroll
        for (int i = 0; i < 8; i++) {
            int idx = tid + i * 256;
            int m = idx >> 5, kk = idx & 31;
            float v = h_s[m * 132 + c * 32 + kk];
            A2[m * 33 + kk] = pk2(v, v);
        }
#pragma unroll
        for (int i = 0; i < 16; i++) B_s[tid + i * 256] = W1[c * 32 * 128 + tid + i * 256];
        __syncthreads();
        gemm2_step<32, 33>(A2, B_s, m0, j, o);
    }
#pragma unroll
    for (int r = 0; r < 8; r++) {
        int gr = row0 + m0 + r;
        if (gr < NN) {
            float2 p0 = upk2(o[r][0]), p1 = upk2(o[r][1]);
            *(float4*)(g_n + gr * HDIM + j) = make_float4(p0.x, p0.y, p1.x, p1.y);
        }
    }
}

// ---------------------------------------------------------------------------
// Edge encoder + scatter: h = relu(x@W0+b0); g_hsum[recv] += h; g_deg[recv]++
// ---------------------------------------------------------------------------
__global__ void __launch_bounds__(256) k_edge_enc_scatter(
        const float* __restrict__ x,
        const float* __restrict__ W0, const float* __restrict__ b0,
        const int* __restrict__ recvs) {
    __shared__ ull   A2[64 * 17];
    __shared__ float B_s[16 * 128];
    __shared__ int   r_idx[64];

    const int tid = threadIdx.x;
    const int ty = tid >> 5, tx = tid & 31;
    const int m0 = ty * 8;
    const int j  = tx * 4;
    const int row0 = blockIdx.x * 64;

#pragma unroll
    for (int i = 0; i < 4; i++) {
        int idx = tid + i * 256;
        int m = idx >> 4, kk = idx & 15;
        float v = x[(row0 + m) * 16 + kk];
        A2[m * 17 + kk] = pk2(v, v);
    }
#pragma unroll
    for (int i = 0; i < 8; i++) B_s[tid + i * 256] = W0[tid + i * 256];
    if (tid < 64) r_idx[tid] = recvs[row0 + tid];
    __syncthreads();

    ull acc[8][2];
    {
        float4 bv = *(const float4*)(b0 + j);
#pragma unroll
        for (int r = 0; r < 8; r++) { acc[r][0] = pk2(bv.x, bv.y); acc[r][1] = pk2(bv.z, bv.w); }
    }
    gemm2_step<16, 17>(A2, B_s, m0, j, acc);

#pragma unroll
    for (int r = 0; r < 8; r++) {
        int rv = r_idx[m0 + r];
        float2 p0 = upk2(acc[r][0]), p1 = upk2(acc[r][1]);
        float v0 = fmaxf(p0.x, 0.f), v1 = fmaxf(p0.y, 0.f);
        float v2 = fmaxf(p1.x, 0.f), v3 = fmaxf(p1.y, 0.f);
        float* dst = g_hsum + (long)rv * HDIM + j;
        asm volatile("red.global.add.v4.f32 [%0], {%1, %2, %3, %4};"
                     :: "l"(dst), "f"(v0), "f"(v1), "f"(v2), "f"(v3) : "memory");
        if (tx == 0) atomicAdd(g_deg + rv, 1.0f);
    }
}

// ---------------------------------------------------------------------------
// c_agg = g_hsum @ g_Wg + g_deg * g_bg
// ---------------------------------------------------------------------------
__global__ void k_cagg() {
    extern __shared__ char smraw[];
    ull*   A2  = (ull*)smraw;                    // [64][33]
    float* B_s = (float*)(smraw + 64 * 33 * 8);  // [32][128]

    const int tid = threadIdx.x;
    const int ty = tid >> 5, tx = tid & 31;
    const int m0 = ty * 8;
    const int j  = tx * 4;
    const int row0 = blockIdx.x * 64;

    ull acc[8][2];
    {
        float4 bgv = *(const float4*)(g_bg + j);
#pragma unroll
        for (int r = 0; r < 8; r++) {
            int gr = row0 + m0 + r;
            float d = (gr < NN) ? g_deg[gr] : 0.f;
            acc[r][0] = pk2(d * bgv.x, d * bgv.y);
            acc[r][1] = pk2(d * bgv.z, d * bgv.w);
        }
    }
    for (int c = 0; c < 4; c++) {
        __syncthreads();
#pragma unroll
        for (int i = 0; i < 8; i++) {
            int idx = tid + i * 256;
            int m = idx >> 5, kk = idx & 31;
            int gr = row0 + m;
            float v = (gr < NN) ? g_hsum[gr * HDIM + c * 32 + kk] : 0.f;
            A2[m * 33 + kk] = pk2(v, v);
        }
#pragma unroll
        for (int i = 0; i < 16; i++) B_s[tid + i * 256] = g_Wg[c * 32 * 128 + tid + i * 256];
        __syncthreads();
        gemm2_step<32, 33>(A2, B_s, m0, j, acc);
    }
#pragma unroll
    for (int r = 0; r < 8; r++) {
        int gr = row0 + m0 + r;
        if (gr < NN) {
            float2 p0 = upk2(acc[r][0]), p1 = upk2(acc[r][1]);
            *(float4*)(g_cagg + gr * HDIM + j) = make_float4(p0.x, p0.y, p1.x, p1.y);
        }
    }
}

// ---------------------------------------------------------------------------
// Per-pass scatter: S[recv] += n[sender]    (pure L2 gather/atomic)
// ---------------------------------------------------------------------------
__global__ void __launch_bounds__(256) k_scatter_n(const int* __restrict__ senders,
                                                   const int* __restrict__ recvs) {
    const int e    = blockIdx.x * 8 + (threadIdx.x >> 5);
    const int lane = threadIdx.x & 31;
    const int j = lane * 4;
    const int s = __ldg(senders + e);
    const int r = __ldg(recvs + e);
    float4 v = *(const float4*)(g_n + (long)s * HDIM + j);
    float* dst = g_S + (long)r * HDIM + j;
    asm volatile("red.global.add.v4.f32 [%0], {%1, %2, %3, %4};"
                 :: "l"(dst), "f"(v.x), "f"(v.y), "f"(v.z), "f"(v.w) : "memory");
}

// ---------------------------------------------------------------------------
// Per-pass node update:
//   h = relu(n@W0_top + S@Wf + c_agg + b0); o = h@W1+b1; n' = LN(n@Wn + o)*g+b
// ---------------------------------------------------------------------------
__global__ void k_node_upd(const float* __restrict__ W0, const float* __restrict__ b0,
                           const float* __restrict__ W1, const float* __restrict__ b1,
                           const float* __restrict__ Wn,
                           const float* __restrict__ lng, const float* __restrict__ lnb) {
    extern __shared__ char smraw[];
    ull*   A2  = (ull*)(smraw + OFF_A2);
    float* h_s = (float*)(smraw + OFF_H);
    float* B_s = (float*)(smraw + OFF_B);

    const int tid = threadIdx.x;
    const int ty = tid >> 5, tx = tid & 31;
    const int m0 = ty * 8;
    const int j  = tx * 4;
    const int row0 = blockIdx.x * 64;

    // hidden: K = 256 over [n | S], weights [W0_top ; Wf], init b0 + c_agg
    ull acc[8][2];
    {
        float4 bv = *(const float4*)(b0 + j);
#pragma unroll
        for (int r = 0; r < 8; r++) {
            int gr = row0 + m0 + r;
            float4 cv = (gr < NN) ? *(const float4*)(g_cagg + gr * HDIM + j)
                                  : make_float4(0.f, 0.f, 0.f, 0.f);
            acc[r][0] = pk2(bv.x + cv.x, bv.y + cv.y);
            acc[r][1] = pk2(bv.z + cv.z, bv.w + cv.w);
        }
    }
    for (int c = 0; c < 8; c++) {
        const float* src  = (c < 4) ? g_n : g_S;
        const float* Bsrc = (c < 4) ? (W0 + c * 32 * 128) : (g_Wf + (c - 4) * 32 * 128);
        int koff = (c & 3) * 32;
        __syncthreads();
#pragma unroll
        for (int i = 0; i < 8; i++) {
            int idx = tid + i * 256;
            int m = idx >> 5, kk = idx & 31;
            int gr = row0 + m;
            float v = (gr < NN) ? src[gr * HDIM + koff + kk] : 0.f;
            A2[m * 33 + kk] = pk2(v, v);
        }
#pragma unroll
        for (int i = 0; i < 16; i++) B_s[tid + i * 256] = Bsrc[tid + i * 256];
        __syncthreads();
        gemm2_step<32, 33>(A2, B_s, m0, j, acc);
    }
    __syncthreads();
#pragma unroll
    for (int r = 0; r < 8; r++) {
        float2 p0 = upk2(acc[r][0]), p1 = upk2(acc[r][1]);
        float4 h;
        h.x = fmaxf(p0.x, 0.f); h.y = fmaxf(p0.y, 0.f);
        h.z = fmaxf(p1.x, 0.f); h.w = fmaxf(p1.y, 0.f);
        *(float4*)(h_s + (m0 + r) * 132 + j) = h;
    }

    // output: K = 128
    ull o[8][2];
    {
        float4 bv = *(const float4*)(b1 + j);
#pragma unroll
        for (int r = 0; r < 8; r++) { o[r][0] = pk2(bv.x, bv.y); o[r][1] = pk2(bv.z, bv.w); }
    }
    for (int c = 0; c < 4; c++) {
        __syncthreads();
#pragma unroll
        for (int i = 0; i < 8; i++) {
            int idx = tid + i * 256;
            int m = idx >> 5, kk = idx & 31;
            float v = h_s[m * 132 + c * 32 + kk];
            A2[m * 33 + kk] = pk2(v, v);
        }
#pragma unroll
        for (int i = 0; i < 16; i++) B_s[tid + i * 256] = W1[c * 32 * 128 + tid + i * 256];
        __syncthreads();
        gemm2_step<32, 33>(A2, B_s, m0, j, o);
    }

    // residual: n @ Wn, K = 128
    ull rr[8][2];
#pragma unroll
    for (int r = 0; r < 8; r++) { rr[r][0] = 0ull; rr[r][1] = 0ull; }
    for (int c = 0; c < 4; c++) {
        __syncthreads();
#pragma unroll
        for (int i = 0; i < 8; i++) {
            int idx = tid + i * 256;
            int m = idx >> 5, kk = idx & 31;
            int gr = row0 + m;
            float v = (gr < NN) ? g_n[gr * HDIM + c * 32 + kk] : 0.f;
            A2[m * 33 + kk] = pk2(v, v);
        }
#pragma unroll
        for (int i = 0; i < 16; i++) B_s[tid + i * 256] = Wn[c * 32 * 128 + tid + i * 256];
        __syncthreads();
        gemm2_step<32, 33>(A2, B_s, m0, j, rr);
    }

    // LayerNorm epilogue
    float4 gv  = *(const float4*)(lng + j);
    float4 bbv = *(const float4*)(lnb + j);
#pragma unroll
    for (int r = 0; r < 8; r++) {
        float2 o0 = upk2(o[r][0]), o1 = upk2(o[r][1]);
        float2 r0 = upk2(rr[r][0]), r1 = upk2(rr[r][1]);
        float t0 = o0.x + r0.x;
        float t1 = o0.y + r0.y;
        float t2 = o1.x + r1.x;
        float t3 = o1.y + r1.y;
        float s1 = t0 + t1 + t2 + t3;
        float s2 = t0*t0 + t1*t1 + t2*t2 + t3*t3;
#pragma unroll
        for (int off = 16; off > 0; off >>= 1) {
            s1 += __shfl_xor_sync(0xffffffffu, s1, off);
            s2 += __shfl_xor_sync(0xffffffffu, s2, off);
        }
        float mu  = s1 * (1.f / 128.f);
        float var = s2 * (1.f / 128.f) - mu * mu;
        float inv = rsqrtf(var + LN_EPS);
        int gr = row0 + m0 + r;
        if (gr < NN) {
            float4 out;
            out.x = (t0 - mu) * inv * gv.x + bbv.x;
            out.y = (t1 - mu) * inv * gv.y + bbv.y;
            out.z = (t2 - mu) * inv * gv.z + bbv.z;
            out.w = (t3 - mu) * inv * gv.w + bbv.w;
            *(float4*)(g_n + gr * HDIM + j) = out;
        }
    }
}

// ---------------------------------------------------------------------------
// Decoder: out = relu(n @ W0 + b0) @ W1 + b1       out: [NN,2]
// ---------------------------------------------------------------------------
__global__ void k_dec(const float* __restrict__ W0, const float* __restrict__ b0,
                      const float* __restrict__ W1, const float* __restrict__ b1,
                      float* __restrict__ out) {
    extern __shared__ char smraw[];
    ull*   A2   = (ull*)(smraw + OFF_A2);
    float* h_s  = (float*)(smraw + OFF_H);
    float* B_s  = (float*)(smraw + OFF_B);
    float* w1_s = (float*)(smraw + SM_BIG);        // [256]
    float* b1_s = w1_s + 256;                       // [2]

    const int tid = threadIdx.x;
    const int ty = tid >> 5, tx = tid & 31;
    const int m0 = ty * 8;
    const int j  = tx * 4;
    const int row0 = blockIdx.x * 64;

    ull acc[8][2];
    {
        float4 bv = *(const float4*)(b0 + j);
#pragma unroll
        for (int r = 0; r < 8; r++) { acc[r][0] = pk2(bv.x, bv.y); acc[r][1] = pk2(bv.z, bv.w); }
    }
    for (int c = 0; c < 4; c++) {
        __syncthreads();
#pragma unroll
        for (int i = 0; i < 8; i++) {
            int idx = tid + i * 256;
            int m = idx >> 5, kk = idx & 31;
            int gr = row0 + m;
            float v = (gr < NN) ? g_n[gr * HDIM + c * 32 + kk] : 0.f;
            A2[m * 33 + kk] = pk2(v, v);
        }
#pragma unroll
        for (int i = 0; i < 16; i++) B_s[tid + i * 256] = W0[c * 32 * 128 + tid + i * 256];
        __syncthreads();
        gemm2_step<32, 33>(A2, B_s, m0, j, acc);
    }
    __syncthreads();
#pragma unroll
    for (int r = 0; r < 8; r++) {
        float2 p0 = upk2(acc[r][0]), p1 = upk2(acc[r][1]);
        float4 h;
        h.x = fmaxf(p0.x, 0.f); h.y = fmaxf(p0.y, 0.f);
        h.z = fmaxf(p1.x, 0.f); h.w = fmaxf(p1.y, 0.f);
        *(float4*)(h_s + (m0 + r) * 132 + j) = h;
    }
    w1_s[tid] = W1[tid];
    if (tid < 2) b1_s[tid] = b1[tid];
    __syncthreads();

    if (tid < 128) {
        int row = tid >> 1, c = tid & 1;
        float s = b1_s[c];
#pragma unroll 8
        for (int k = 0; k < 128; k++)
            s = fmaf(h_s[row * 132 + k], w1_s[k * 2 + c], s);
        int gr = row0 + row;
        if (gr < NN) out[gr * 2 + c] = s;
    }
}

// ---------------------------------------------------------------------------
extern "C" void kernel_launch(void* const* d_in, const int* in_sizes, int n_in,
                              void* d_out, int out_size) {
    const float* nodes   = (const float*)d_in[0];
    const float* edges   = (const float*)d_in[1];
    const int*   senders = (const int*)  d_in[2];
    const int*   recvs   = (const int*)  d_in[3];
    const float* enW0 = (const float*)d_in[4];
    const float* enb0 = (const float*)d_in[5];
    const float* enW1 = (const float*)d_in[6];
    const float* enb1 = (const float*)d_in[7];
    const float* eeW0 = (const float*)d_in[8];
    const float* eeb0 = (const float*)d_in[9];
    const float* eeW1 = (const float*)d_in[10];
    const float* eeb1 = (const float*)d_in[11];
    const float* Wmsg = (const float*)d_in[12];
    const float* nW0  = (const float*)d_in[13];
    const float* nb0  = (const float*)d_in[14];
    const float* nW1  = (const float*)d_in[15];
    const float* nb1  = (const float*)d_in[16];
    const float* Wnode= (const float*)d_in[17];
    const float* lng  = (const float*)d_in[18];
    const float* lnb  = (const float*)d_in[19];
    const float* dW0  = (const float*)d_in[20];
    const float* db0  = (const float*)d_in[21];
    const float* dW1  = (const float*)d_in[22];
    const float* db1  = (const float*)d_in[23];
    float* out = (float*)d_out;

    const int SM_CAGG = 64 * 33 * 8 + 32 * 128 * 4;   // 33280
    const int SM_DEC  = SM_BIG + 258 * 4;              // 68104

    cudaFuncSetAttribute(k_node_enc, cudaFuncAttributeMaxDynamicSharedMemorySize, SM_BIG);
    cudaFuncSetAttribute(k_cagg,     cudaFuncAttributeMaxDynamicSharedMemorySize, SM_CAGG);
    cudaFuncSetAttribute(k_node_upd, cudaFuncAttributeMaxDynamicSharedMemorySize, SM_BIG);
    cudaFuncSetAttribute(k_dec,      cudaFuncAttributeMaxDynamicSharedMemorySize, SM_DEC);

    // Folds + invariants
    k_fold1<<<129, 128>>>(eeW1, eeb1, Wmsg);
    k_fold2<<<257, 128>>>(nW0, Wmsg);
    k_zero_pre<<<(NN * 32 + NN / 4 + 255) / 256, 256>>>();
    k_node_enc<<<NODE_TILES, 256, SM_BIG>>>(nodes, enW0, enb0, enW1, enb1);
    k_edge_enc_scatter<<<EDGE_TILES, 256>>>(edges, eeW0, eeb0, recvs);
    k_cagg<<<NODE_TILES, 256, SM_CAGG>>>();

    for (int p = 0; p < NPASS; p++) {
        k_zero_S<<<(NN * 32 + 255) / 256, 256>>>();
        k_scatter_n<<<NEDGE / 8, 256>>>(senders, recvs);
        k_node_upd<<<NODE_TILES, 256, SM_BIG>>>(nW0, nb0, nW1, nb1, Wnode, lng, lnb);
    }

    k_dec<<<NODE_TILES, 256, SM_DEC>>>(dW0, db0, dW1, db1, out);
}